// round 11
// baseline (speedup 1.0000x reference)
#include <cuda_runtime.h>
#include <cuda_bf16.h>

// ============================================================================
// Sinkhorn, N=8, P=2048, EPS=0.1, 50 iters.
//   a = (mu+1e-8)/(K b),  b = (nu+1e-8)/(K^T a),  b0 = 1,  K = exp(-C/eps)
// K stored as bf16 pairs (67MB, L2-resident); bf16->fp32 expansion is pure
// ALU (shift/mask). ONE persistent kernel, per-batch software barriers.
// Each thread owns 8 fixed columns. Band loop is SOFTWARE-PIPELINED: the
// next band's 8 LDG.128 are issued before the current band's compute, so
// L2 latency (~260cyc) overlaps pass1 + both __syncthreads + pass2.
// K traverses L2 once per iteration. Deterministic (fixed reduction order).
//
// Output (fp32): [ cost(8) | pi(8*2048*2048) | C(8*2048*2048) ],
// pi recomputed from ORIGINAL fp32 C: pi = exp(ln a_i + ln b_j - 10*C_ij).
// ============================================================================

#define N_B   8
#define P     2048
#define NITER 50
#define RB    8                 // rows per band
#define NBANDS (P / RB)         // 256 bands per batch
#define TPB   256
#define MAXBB 64                // max blocks per batch (partials bound)
#define INV_EPS 10.0f

// scratch (static __device__ arrays: the sanctioned scratch mechanism)
static __device__ unsigned  K2[(size_t)N_B * P * (P / 2)];     // 67 MB bf16x2
static __device__ float     partials[(size_t)N_B * MAXBB * P]; // 4 MB
static __device__ float     b_buf[N_B * P];
static __device__ float     a_buf[N_B * P];
static __device__ float     cost_part[N_B * 128];

// per-batch software barriers (zero-init; ctr returns to 0, gen monotonic)
static __device__ unsigned bbar_ctr[N_B];
static __device__ volatile unsigned bbar_gen[N_B];

__device__ __forceinline__ void batch_sync(int n, int Bb) {
    __syncthreads();
    if (threadIdx.x == 0) {
        __threadfence();
        unsigned gen = bbar_gen[n];
        if (atomicAdd(&bbar_ctr[n], 1u) == (unsigned)(Bb - 1)) {
            bbar_ctr[n] = 0;
            __threadfence();
            bbar_gen[n] = gen + 1;
        } else {
            while (bbar_gen[n] == gen) { }
            __threadfence();
        }
    }
    __syncthreads();
}

// bf16-pair -> two floats, pure ALU (no F2F)
__device__ __forceinline__ float blo(unsigned u) { return __uint_as_float(u << 16); }
__device__ __forceinline__ float bhi(unsigned u) { return __uint_as_float(u & 0xFFFF0000u); }

// ---------------------------------------------------------------------------
// K = exp(-C/eps), fp32 -> bf16 pairs
__global__ __launch_bounds__(256) void k_prep(const float* __restrict__ C) {
    size_t i = (size_t)blockIdx.x * 256 + threadIdx.x;  // float4 idx, 8388608
    float4 c = __ldcs(reinterpret_cast<const float4*>(C) + i);
    __nv_bfloat162 h0 = __floats2bfloat162_rn(__expf(-INV_EPS * c.x),
                                              __expf(-INV_EPS * c.y));
    __nv_bfloat162 h1 = __floats2bfloat162_rn(__expf(-INV_EPS * c.z),
                                              __expf(-INV_EPS * c.w));
    K2[2 * i]     = *reinterpret_cast<unsigned*>(&h0);
    K2[2 * i + 1] = *reinterpret_cast<unsigned*>(&h1);
}

// ---------------------------------------------------------------------------
// Persistent iteration kernel. grid = G = 8*Bb blocks, 256 threads.
__global__ __launch_bounds__(TPB) void k_main(const float* __restrict__ mu,
                                              const float* __restrict__ nu,
                                              int Bb) {
    __shared__ float wsum[RB * 8];   // [row][warp] partials
    __shared__ float ash[RB];        // a for current band

    int tid = threadIdx.x;
    int w   = tid >> 5;
    int l   = tid & 31;
    int n   = blockIdx.x / Bb;       // batch
    int r   = blockIdx.x % Bb;       // block index within batch

    const unsigned* Kbase = K2 + (size_t)n * P * (P / 2);

    // b0 = 1 (each batch inits its own slice)
    for (int e = r * TPB + tid; e < P; e += Bb * TPB)
        b_buf[n * P + e] = 1.0f;
    batch_sync(n, Bb);

    for (int it = 0; it < NITER; it++) {
        // this thread's 8 b-values (columns 8*tid .. 8*tid+7)
        const float4* bb4 = reinterpret_cast<const float4*>(b_buf + n * P) + tid * 2;
        float4 B0 = __ldcg(bb4);
        float4 B1 = __ldcg(bb4 + 1);

        float c0 = 0.f, c1 = 0.f, c2 = 0.f, c3 = 0.f;
        float c4 = 0.f, c5 = 0.f, c6 = 0.f, c7 = 0.f;

        // ---- software-pipelined band loop (register double buffer) ----
        uint4 bufA[RB], bufB[RB];

        auto loadband = [&](uint4* kk, int band) {
            const uint4* Kb = reinterpret_cast<const uint4*>(
                Kbase + (size_t)band * RB * (P / 2));
#pragma unroll
            for (int i = 0; i < RB; i++)
                kk[i] = Kb[(size_t)i * 256 + tid];
        };

        auto process = [&](uint4* kk, int band) {
            // pass 1: row dots with register b, warp shfl-reduce
#pragma unroll
            for (int i = 0; i < RB; i++) {
                float s = blo(kk[i].x) * B0.x;
                s = fmaf(bhi(kk[i].x), B0.y, s);
                s = fmaf(blo(kk[i].y), B0.z, s);
                s = fmaf(bhi(kk[i].y), B0.w, s);
                s = fmaf(blo(kk[i].z), B1.x, s);
                s = fmaf(bhi(kk[i].z), B1.y, s);
                s = fmaf(blo(kk[i].w), B1.z, s);
                s = fmaf(bhi(kk[i].w), B1.w, s);
#pragma unroll
                for (int o = 16; o; o >>= 1)
                    s += __shfl_down_sync(0xffffffffu, s, o);
                if (l == 0) wsum[i * 8 + w] = s;
            }
            __syncthreads();
            if (tid < RB) {
                float s = 0.f;
#pragma unroll
                for (int j = 0; j < 8; j++) s += wsum[tid * 8 + j];
                int row = band * RB + tid;
                float av = __fdividef(__ldg(mu + n * P + row) + 1e-8f, s);
                ash[tid] = av;
                if (it == NITER - 1) a_buf[n * P + row] = av;
            }
            __syncthreads();
            // pass 2: column partials from the same registers
#pragma unroll
            for (int i = 0; i < RB; i++) {
                float ai = ash[i];
                c0 = fmaf(ai, blo(kk[i].x), c0);  c1 = fmaf(ai, bhi(kk[i].x), c1);
                c2 = fmaf(ai, blo(kk[i].y), c2);  c3 = fmaf(ai, bhi(kk[i].y), c3);
                c4 = fmaf(ai, blo(kk[i].z), c4);  c5 = fmaf(ai, bhi(kk[i].z), c5);
                c6 = fmaf(ai, blo(kk[i].w), c6);  c7 = fmaf(ai, bhi(kk[i].w), c7);
            }
            // ash/wsum rewritten only after the next band's own syncs.
        };

        int band = r;
        loadband(bufA, band);
        bool useA = true;
        for (; band < NBANDS; band += Bb) {
            int nxt = band + Bb;
            if (useA) {
                if (nxt < NBANDS) loadband(bufB, nxt);   // prefetch overlaps
                process(bufA, band);
            } else {
                if (nxt < NBANDS) loadband(bufA, nxt);
                process(bufB, band);
            }
            useA = !useA;
        }

        // publish this block's column partials
        float* wp = partials + (size_t)(n * Bb + r) * P + tid * 8;
        *reinterpret_cast<float4*>(wp)     = make_float4(c0, c1, c2, c3);
        *reinterpret_cast<float4*>(wp + 4) = make_float4(c4, c5, c6, c7);

        batch_sync(n, Bb);

        // distributed b-reduce (batch-local): 4 threads per column entry,
        // 4 independent accumulators for MLP, shfl-combine in 4-lane groups.
        {
            int t = r * TPB + tid;              // 0 .. Bb*256-1
            int e = t >> 2;                     // column entry
            int q = t & 3;                      // lane within 4-group
            float s0 = 0.f, s1 = 0.f, s2 = 0.f, s3 = 0.f;
            if (e < P) {
                const float* pp = partials + (size_t)n * Bb * P + e;
                int k = q;
                for (; k + 12 < Bb; k += 16) {
                    s0 += __ldcg(pp + (size_t)k * P);
                    s1 += __ldcg(pp + (size_t)(k + 4) * P);
                    s2 += __ldcg(pp + (size_t)(k + 8) * P);
                    s3 += __ldcg(pp + (size_t)(k + 12) * P);
                }
                for (; k < Bb; k += 4) s0 += __ldcg(pp + (size_t)k * P);
            }
            float s = (s0 + s1) + (s2 + s3);
            s += __shfl_down_sync(0xffffffffu, s, 1, 4);
            s += __shfl_down_sync(0xffffffffu, s, 2, 4);
            if (e < P && q == 0)
                b_buf[n * P + e] = __fdividef(__ldg(nu + n * P + e) + 1e-8f, s);
        }

        batch_sync(n, Bb);
    }
}

// ---------------------------------------------------------------------------
// pi = exp(ln a + ln b - 10*C) from ORIGINAL fp32 C; cost partials; C copy
__global__ __launch_bounds__(256) void k_epi(const float* __restrict__ C,
                                             float* __restrict__ pi_out,
                                             float* __restrict__ c_out) {
    int n    = blockIdx.y;
    int row0 = blockIdx.x * 16;
    __shared__ float lbsh[P];
    __shared__ float sred[256];
    for (int j = threadIdx.x; j < P; j += 256)
        lbsh[j] = __logf(b_buf[n * P + j]);
    __syncthreads();
    float local = 0.0f;
    for (int r = 0; r < 16; r++) {
        int row = row0 + r;
        float la = __logf(a_buf[n * P + row]);
        size_t base = ((size_t)n * P + row) * P;
        const float4* Cr = reinterpret_cast<const float4*>(C + base);
        float4* Pr = pi_out ? reinterpret_cast<float4*>(pi_out + base) : nullptr;
        float4* Or = c_out  ? reinterpret_cast<float4*>(c_out  + base) : nullptr;
        for (int q = threadIdx.x; q < P / 4; q += 256) {
            float4 c = __ldcs(Cr + q);
            int j = q * 4;
            float4 pi;
            pi.x = __expf(la + lbsh[j]     - INV_EPS * c.x);
            pi.y = __expf(la + lbsh[j + 1] - INV_EPS * c.y);
            pi.z = __expf(la + lbsh[j + 2] - INV_EPS * c.z);
            pi.w = __expf(la + lbsh[j + 3] - INV_EPS * c.w);
            if (Pr) __stcs(Pr + q, pi);
            if (Or) __stcs(Or + q, c);
            local += pi.x * c.x + pi.y * c.y + pi.z * c.z + pi.w * c.w;
        }
    }
    sred[threadIdx.x] = local;
    __syncthreads();
    for (int o = 128; o; o >>= 1) {
        if (threadIdx.x < o) sred[threadIdx.x] += sred[threadIdx.x + o];
        __syncthreads();
    }
    if (threadIdx.x == 0) cost_part[n * 128 + blockIdx.x] = sred[0];
}

__global__ __launch_bounds__(128) void k_cost(float* __restrict__ out) {
    int n = blockIdx.x;
    __shared__ float s[128];
    s[threadIdx.x] = cost_part[n * 128 + threadIdx.x];
    __syncthreads();
    for (int o = 64; o; o >>= 1) {
        if (threadIdx.x < o) s[threadIdx.x] += s[threadIdx.x + o];
        __syncthreads();
    }
    if (threadIdx.x == 0) out[n] = s[0];
}

// ---------------------------------------------------------------------------
extern "C" void kernel_launch(void* const* d_in, const int* in_sizes, int n_in,
                              void* d_out, int out_size) {
    const float* C  = (const float*)d_in[0];
    const float* mu = (const float*)d_in[1];
    const float* nu = (const float*)d_in[2];
    float* out = (float*)d_out;

    const long long PI_ELEMS = (long long)N_B * P * P;  // 33554432
    float* pi_out = nullptr;
    float* c_out  = nullptr;
    if ((long long)out_size >= 8 + PI_ELEMS)     pi_out = out + 8;
    if ((long long)out_size >= 8 + 2 * PI_ELEMS) c_out  = out + 8 + PI_ELEMS;

    static int G = 0, Bb = 0;
    if (G == 0) {   // host-side, deterministic per process
        int dev = 0, nsm = 148, maxb = 1;
        cudaGetDevice(&dev);
        cudaDeviceGetAttribute(&nsm, cudaDevAttrMultiProcessorCount, dev);
        cudaOccupancyMaxActiveBlocksPerMultiprocessor(&maxb, k_main, TPB, 0);
        if (maxb < 1) maxb = 1;
        if (maxb > 2) maxb = 2;  // avoid occ-3 regime (R10 regression)
        long long tot = (long long)nsm * maxb;
        Bb = (int)(tot / N_B);
        if (Bb > MAXBB) Bb = MAXBB;
        if (Bb < 32) Bb = 32;   // b-reduce needs Bb*256 >= 4*P threads
        G = Bb * N_B;
    }

    k_prep<<<32768, 256>>>(C);
    k_main<<<G, TPB>>>(mu, nu, Bb);
    k_epi<<<dim3(128, N_B), 256>>>(C, pi_out, c_out);
    k_cost<<<N_B, 128>>>(out);
}

// round 13
// speedup vs baseline: 1.3171x; 1.3171x over previous
#include <cuda_runtime.h>
#include <cuda_bf16.h>

// ============================================================================
// Sinkhorn, N=8, P=2048, EPS=0.1, 50 iters.
//   a = (mu+1e-8)/(K b),  b = (nu+1e-8)/(K^T a),  b0 = 1,  K = exp(-C/eps)
// K stored as bf16 pairs (67MB, L2-resident); bf16->fp32 expansion is pure
// ALU (shift/mask). ONE persistent kernel, per-batch software barriers.
// Band loop pipelined via cp.async into a TRIPLE-BUFFERED smem staging area
// (zero register cost -> no spills, occ 2): band k+1 streams global->smem
// while band k computes, hiding L2 latency across the per-band syncs.
// K traverses L2 once per iteration. Deterministic (fixed reduction order).
//
// Output (fp32): [ cost(8) | pi(8*2048*2048) | C(8*2048*2048) ],
// pi recomputed from ORIGINAL fp32 C: pi = exp(ln a_i + ln b_j - 10*C_ij).
// ============================================================================

#define N_B   8
#define P     2048
#define NITER 50
#define RB    8                 // rows per band
#define NBANDS (P / RB)         // 256 bands per batch
#define TPB   256
#define MAXBB 64                // max blocks per batch (partials bound)
#define INV_EPS 10.0f
#define BAND_U4 (RB * 256)      // uint4 per band (8 rows * 256)

// scratch (static __device__ arrays: the sanctioned scratch mechanism)
static __device__ unsigned  K2[(size_t)N_B * P * (P / 2)];     // 67 MB bf16x2
static __device__ float     partials[(size_t)N_B * MAXBB * P]; // 4 MB
static __device__ float     b_buf[N_B * P];
static __device__ float     a_buf[N_B * P];
static __device__ float     cost_part[N_B * 128];

// per-batch software barriers (zero-init; ctr returns to 0, gen monotonic)
static __device__ unsigned bbar_ctr[N_B];
static __device__ volatile unsigned bbar_gen[N_B];

__device__ __forceinline__ void batch_sync(int n, int Bb) {
    __syncthreads();
    if (threadIdx.x == 0) {
        __threadfence();
        unsigned gen = bbar_gen[n];
        if (atomicAdd(&bbar_ctr[n], 1u) == (unsigned)(Bb - 1)) {
            bbar_ctr[n] = 0;
            __threadfence();
            bbar_gen[n] = gen + 1;
        } else {
            while (bbar_gen[n] == gen) { }
            __threadfence();
        }
    }
    __syncthreads();
}

// bf16-pair -> two floats, pure ALU (no F2F)
__device__ __forceinline__ float blo(unsigned u) { return __uint_as_float(u << 16); }
__device__ __forceinline__ float bhi(unsigned u) { return __uint_as_float(u & 0xFFFF0000u); }

// cp.async helpers
__device__ __forceinline__ void cp16(void* dst_smem, const void* src) {
    unsigned d = (unsigned)__cvta_generic_to_shared(dst_smem);
    asm volatile("cp.async.cg.shared.global [%0], [%1], 16;\n" :: "r"(d), "l"(src));
}
__device__ __forceinline__ void cp_commit() {
    asm volatile("cp.async.commit_group;\n" ::: "memory");
}
template <int N> __device__ __forceinline__ void cp_wait() {
    asm volatile("cp.async.wait_group %0;\n" :: "n"(N) : "memory");
}

// ---------------------------------------------------------------------------
// K = exp(-C/eps), fp32 -> bf16 pairs
__global__ __launch_bounds__(256) void k_prep(const float* __restrict__ C) {
    size_t i = (size_t)blockIdx.x * 256 + threadIdx.x;  // float4 idx, 8388608
    float4 c = __ldcs(reinterpret_cast<const float4*>(C) + i);
    __nv_bfloat162 h0 = __floats2bfloat162_rn(__expf(-INV_EPS * c.x),
                                              __expf(-INV_EPS * c.y));
    __nv_bfloat162 h1 = __floats2bfloat162_rn(__expf(-INV_EPS * c.z),
                                              __expf(-INV_EPS * c.w));
    K2[2 * i]     = *reinterpret_cast<unsigned*>(&h0);
    K2[2 * i + 1] = *reinterpret_cast<unsigned*>(&h1);
}

// ---------------------------------------------------------------------------
// Persistent iteration kernel. grid = G = 8*Bb blocks, 256 threads.
// dynamic smem: kbuf[3][BAND_U4] uint4 (96KB) | wsum[64] | ash[8]
extern __shared__ char smem_raw[];
__global__ __launch_bounds__(TPB) void k_main(const float* __restrict__ mu,
                                              const float* __restrict__ nu,
                                              int Bb) {
    uint4* kbuf  = reinterpret_cast<uint4*>(smem_raw);           // 3 * 4096 u4
    float* wsum  = reinterpret_cast<float*>(smem_raw + 3 * BAND_U4 * 16);
    float* ash   = wsum + 64;

    int tid = threadIdx.x;
    int w   = tid >> 5;
    int l   = tid & 31;
    int n   = blockIdx.x / Bb;       // batch
    int r   = blockIdx.x % Bb;       // block index within batch

    const unsigned* Kbase = K2 + (size_t)n * P * (P / 2);

    // b0 = 1 (each batch inits its own slice)
    for (int e = r * TPB + tid; e < P; e += Bb * TPB)
        b_buf[n * P + e] = 1.0f;
    batch_sync(n, Bb);

    for (int it = 0; it < NITER; it++) {
        // this thread's 8 b-values (columns 8*tid .. 8*tid+7)
        const float4* bb4 = reinterpret_cast<const float4*>(b_buf + n * P) + tid * 2;
        float4 B0 = __ldcg(bb4);
        float4 B1 = __ldcg(bb4 + 1);

        float c0 = 0.f, c1 = 0.f, c2 = 0.f, c3 = 0.f;
        float c4 = 0.f, c5 = 0.f, c6 = 0.f, c7 = 0.f;

        // stage band `band` into buffer slot `slot` (128B per thread)
        auto stage = [&](int slot, int band) {
            const uint4* src = reinterpret_cast<const uint4*>(
                Kbase + (size_t)band * RB * (P / 2));
            uint4* dst = kbuf + slot * BAND_U4;
#pragma unroll
            for (int i = 0; i < RB; i++)
                cp16(dst + i * 256 + tid, src + (size_t)i * 256 + tid);
            cp_commit();
        };

        // ---- pipelined band loop ----
        stage(0, r);
        int cnt = 0;
        for (int band = r; band < NBANDS; band += Bb, cnt++) {
            int nxt = band + Bb;
            if (nxt < NBANDS) { stage((cnt + 1) % 3, nxt); cp_wait<1>(); }
            else              { cp_wait<0>(); }
            __syncthreads();   // staged data visible to all threads

            const uint4* kb = kbuf + (cnt % 3) * BAND_U4;

            // pass 1: row dots with register b, warp shfl-reduce
#pragma unroll
            for (int i = 0; i < RB; i++) {
                uint4 kk = kb[i * 256 + tid];
                float s = blo(kk.x) * B0.x;
                s = fmaf(bhi(kk.x), B0.y, s);
                s = fmaf(blo(kk.y), B0.z, s);
                s = fmaf(bhi(kk.y), B0.w, s);
                s = fmaf(blo(kk.z), B1.x, s);
                s = fmaf(bhi(kk.z), B1.y, s);
                s = fmaf(blo(kk.w), B1.z, s);
                s = fmaf(bhi(kk.w), B1.w, s);
#pragma unroll
                for (int o = 16; o; o >>= 1)
                    s += __shfl_down_sync(0xffffffffu, s, o);
                if (l == 0) wsum[i * 8 + w] = s;
            }
            __syncthreads();

            if (tid < RB) {
                float s = 0.f;
#pragma unroll
                for (int j = 0; j < 8; j++) s += wsum[tid * 8 + j];
                int row = band * RB + tid;
                float av = __fdividef(__ldg(mu + n * P + row) + 1e-8f, s);
                ash[tid] = av;
                if (it == NITER - 1) a_buf[n * P + row] = av;
            }
            __syncthreads();

            // pass 2: column partials, re-reading the smem band
#pragma unroll
            for (int i = 0; i < RB; i++) {
                float ai = ash[i];
                uint4 kk = kb[i * 256 + tid];
                c0 = fmaf(ai, blo(kk.x), c0);  c1 = fmaf(ai, bhi(kk.x), c1);
                c2 = fmaf(ai, blo(kk.y), c2);  c3 = fmaf(ai, bhi(kk.y), c3);
                c4 = fmaf(ai, blo(kk.z), c4);  c5 = fmaf(ai, bhi(kk.z), c5);
                c6 = fmaf(ai, blo(kk.w), c6);  c7 = fmaf(ai, bhi(kk.w), c7);
            }
            // slot reused only at cnt+3; barriers of the next iterations
            // order all pass-2 reads before that restage.
        }

        // publish this block's column partials
        float* wp = partials + (size_t)(n * Bb + r) * P + tid * 8;
        *reinterpret_cast<float4*>(wp)     = make_float4(c0, c1, c2, c3);
        *reinterpret_cast<float4*>(wp + 4) = make_float4(c4, c5, c6, c7);

        batch_sync(n, Bb);

        // distributed b-reduce (batch-local): 4 threads per column entry,
        // 4 independent accumulators for MLP, shfl-combine in 4-lane groups.
        {
            int t = r * TPB + tid;              // 0 .. Bb*256-1
            int e = t >> 2;                     // column entry
            int q = t & 3;                      // lane within 4-group
            float s0 = 0.f, s1 = 0.f, s2 = 0.f, s3 = 0.f;
            if (e < P) {
                const float* pp = partials + (size_t)n * Bb * P + e;
                int k = q;
                for (; k + 12 < Bb; k += 16) {
                    s0 += __ldcg(pp + (size_t)k * P);
                    s1 += __ldcg(pp + (size_t)(k + 4) * P);
                    s2 += __ldcg(pp + (size_t)(k + 8) * P);
                    s3 += __ldcg(pp + (size_t)(k + 12) * P);
                }
                for (; k < Bb; k += 4) s0 += __ldcg(pp + (size_t)k * P);
            }
            float s = (s0 + s1) + (s2 + s3);
            s += __shfl_down_sync(0xffffffffu, s, 1, 4);
            s += __shfl_down_sync(0xffffffffu, s, 2, 4);
            if (e < P && q == 0)
                b_buf[n * P + e] = __fdividef(__ldg(nu + n * P + e) + 1e-8f, s);
        }

        batch_sync(n, Bb);
    }
}

// ---------------------------------------------------------------------------
// pi = exp(ln a + ln b - 10*C) from ORIGINAL fp32 C; cost partials; C copy
__global__ __launch_bounds__(256) void k_epi(const float* __restrict__ C,
                                             float* __restrict__ pi_out,
                                             float* __restrict__ c_out) {
    int n    = blockIdx.y;
    int row0 = blockIdx.x * 16;
    __shared__ float lbsh[P];
    __shared__ float sred[256];
    for (int j = threadIdx.x; j < P; j += 256)
        lbsh[j] = __logf(b_buf[n * P + j]);
    __syncthreads();
    float local = 0.0f;
    for (int r = 0; r < 16; r++) {
        int row = row0 + r;
        float la = __logf(a_buf[n * P + row]);
        size_t base = ((size_t)n * P + row) * P;
        const float4* Cr = reinterpret_cast<const float4*>(C + base);
        float4* Pr = pi_out ? reinterpret_cast<float4*>(pi_out + base) : nullptr;
        float4* Or = c_out  ? reinterpret_cast<float4*>(c_out  + base) : nullptr;
        for (int q = threadIdx.x; q < P / 4; q += 256) {
            float4 c = __ldcs(Cr + q);
            int j = q * 4;
            float4 pi;
            pi.x = __expf(la + lbsh[j]     - INV_EPS * c.x);
            pi.y = __expf(la + lbsh[j + 1] - INV_EPS * c.y);
            pi.z = __expf(la + lbsh[j + 2] - INV_EPS * c.z);
            pi.w = __expf(la + lbsh[j + 3] - INV_EPS * c.w);
            if (Pr) __stcs(Pr + q, pi);
            if (Or) __stcs(Or + q, c);
            local += pi.x * c.x + pi.y * c.y + pi.z * c.z + pi.w * c.w;
        }
    }
    sred[threadIdx.x] = local;
    __syncthreads();
    for (int o = 128; o; o >>= 1) {
        if (threadIdx.x < o) sred[threadIdx.x] += sred[threadIdx.x + o];
        __syncthreads();
    }
    if (threadIdx.x == 0) cost_part[n * 128 + blockIdx.x] = sred[0];
}

__global__ __launch_bounds__(128) void k_cost(float* __restrict__ out) {
    int n = blockIdx.x;
    __shared__ float s[128];
    s[threadIdx.x] = cost_part[n * 128 + threadIdx.x];
    __syncthreads();
    for (int o = 64; o; o >>= 1) {
        if (threadIdx.x < o) s[threadIdx.x] += s[threadIdx.x + o];
        __syncthreads();
    }
    if (threadIdx.x == 0) out[n] = s[0];
}

// ---------------------------------------------------------------------------
extern "C" void kernel_launch(void* const* d_in, const int* in_sizes, int n_in,
                              void* d_out, int out_size) {
    const float* C  = (const float*)d_in[0];
    const float* mu = (const float*)d_in[1];
    const float* nu = (const float*)d_in[2];
    float* out = (float*)d_out;

    const long long PI_ELEMS = (long long)N_B * P * P;  // 33554432
    float* pi_out = nullptr;
    float* c_out  = nullptr;
    if ((long long)out_size >= 8 + PI_ELEMS)     pi_out = out + 8;
    if ((long long)out_size >= 8 + 2 * PI_ELEMS) c_out  = out + 8 + PI_ELEMS;

    const int MAIN_SMEM = 3 * BAND_U4 * 16 + 64 * 4 + 8 * 4 + 32;  // ~96.4 KB
    static int G = 0, Bb = 0;
    if (G == 0) {   // host-side, deterministic per process
        cudaFuncSetAttribute(k_main, cudaFuncAttributeMaxDynamicSharedMemorySize,
                             MAIN_SMEM);
        int dev = 0, nsm = 148, maxb = 1;
        cudaGetDevice(&dev);
        cudaDeviceGetAttribute(&nsm, cudaDevAttrMultiProcessorCount, dev);
        cudaOccupancyMaxActiveBlocksPerMultiprocessor(&maxb, k_main, TPB, MAIN_SMEM);
        if (maxb < 1) maxb = 1;
        if (maxb > 2) maxb = 2;
        long long tot = (long long)nsm * maxb;
        Bb = (int)(tot / N_B);
        if (Bb > MAXBB) Bb = MAXBB;
        if (Bb < 32) Bb = 32;   // b-reduce needs Bb*256 >= 4*P threads
        G = Bb * N_B;
    }

    k_prep<<<32768, 256>>>(C);
    k_main<<<G, TPB, MAIN_SMEM>>>(mu, nu, Bb);
    k_epi<<<dim3(128, N_B), 256>>>(C, pi_out, c_out);
    k_cost<<<N_B, 128>>>(out);
}

// round 15
// speedup vs baseline: 1.6838x; 1.2784x over previous
#include <cuda_runtime.h>
#include <cuda_fp16.h>

// ============================================================================
// Sinkhorn, N=8, P=2048, EPS=0.1, 50 iters.
//   a = (mu+1e-8)/(K b),  b = (nu+1e-8)/(K^T a),  b0 = 1,  K = exp(-C/eps)
// K fp16 (67MB, L2-resident). ONE persistent kernel, per-batch software
// barriers. Structure is EXACTLY the proven R9 layout (each thread owns 8
// columns; per 8-row band K sits in 32 registers reused by pass1 row-GEMV
// and pass2 column partials), plus: each block caches its FIRST 3 BANDS in
// 96KB persistent SMEM (written on iteration 0, per-thread-private slots),
// cutting per-iteration L2 K-traffic by ~43% (67MB -> 38MB).
// Deterministic (fixed reduction order, no float atomics).
//
// Output (fp32): [ cost(8) | pi(8*2048*2048) | C(8*2048*2048) ],
// pi recomputed from ORIGINAL fp32 C: pi = exp(ln a_i + ln b_j - 10*C_ij).
// ============================================================================

#define N_B   8
#define P     2048
#define NITER 50
#define RB    8                 // rows per band
#define NBANDS (P / RB)         // 256 bands per batch
#define TPB   256
#define MAXBB 64                // max blocks per batch (partials bound)
#define CB    3                 // bands cached in smem per block
#define BAND_U4 (RB * 256)      // uint4 per band
#define INV_EPS 10.0f

// scratch (static __device__ arrays: the sanctioned scratch mechanism)
static __device__ __half2   K2[(size_t)N_B * P * (P / 2)];     // 67 MB fp16
static __device__ float     partials[(size_t)N_B * MAXBB * P]; // 4 MB
static __device__ float     b_buf[N_B * P];
static __device__ float     a_buf[N_B * P];
static __device__ float     cost_part[N_B * 128];

// per-batch software barriers (zero-init; ctr returns to 0, gen monotonic)
static __device__ unsigned bbar_ctr[N_B];
static __device__ volatile unsigned bbar_gen[N_B];

__device__ __forceinline__ void batch_sync(int n, int Bb) {
    __syncthreads();
    if (threadIdx.x == 0) {
        __threadfence();
        unsigned gen = bbar_gen[n];
        if (atomicAdd(&bbar_ctr[n], 1u) == (unsigned)(Bb - 1)) {
            bbar_ctr[n] = 0;
            __threadfence();
            bbar_gen[n] = gen + 1;
        } else {
            while (bbar_gen[n] == gen) { }
            __threadfence();
        }
    }
    __syncthreads();
}

// ---------------------------------------------------------------------------
// K = exp(-C/eps), fp32 -> fp16
__global__ __launch_bounds__(256) void k_prep(const float* __restrict__ C) {
    size_t i = (size_t)blockIdx.x * 256 + threadIdx.x;  // float4 idx, 8388608
    float4 c = __ldcs(reinterpret_cast<const float4*>(C) + i);
    K2[2 * i]     = __floats2half2_rn(__expf(-INV_EPS * c.x), __expf(-INV_EPS * c.y));
    K2[2 * i + 1] = __floats2half2_rn(__expf(-INV_EPS * c.z), __expf(-INV_EPS * c.w));
}

// ---------------------------------------------------------------------------
// Persistent iteration kernel. grid = G = 8*Bb blocks, 256 threads.
// dynamic smem: kcache[CB*BAND_U4] uint4 (96KB) | wsum[64] | ash[8]
extern __shared__ char smem_raw[];
__global__ __launch_bounds__(TPB) void k_main(const float* __restrict__ mu,
                                              const float* __restrict__ nu,
                                              int Bb) {
    uint4* kcache = reinterpret_cast<uint4*>(smem_raw);
    float* wsum   = reinterpret_cast<float*>(smem_raw + CB * BAND_U4 * 16);
    float* ash    = wsum + 64;

    int tid = threadIdx.x;
    int w   = tid >> 5;
    int l   = tid & 31;
    int n   = blockIdx.x / Bb;       // batch
    int r   = blockIdx.x % Bb;       // block index within batch

    // b0 = 1 (each batch inits its own slice)
    for (int e = r * TPB + tid; e < P; e += Bb * TPB)
        b_buf[n * P + e] = 1.0f;
    batch_sync(n, Bb);

    for (int it = 0; it < NITER; it++) {
        // this thread's 8 b-values (columns 8*tid .. 8*tid+7)
        const float4* bb4 = reinterpret_cast<const float4*>(b_buf + n * P) + tid * 2;
        float4 B0 = __ldcg(bb4);
        float4 B1 = __ldcg(bb4 + 1);

        float c0 = 0.f, c1 = 0.f, c2 = 0.f, c3 = 0.f;
        float c4 = 0.f, c5 = 0.f, c6 = 0.f, c7 = 0.f;

        int cnt = 0;
        for (int band = r; band < NBANDS; band += Bb, cnt++) {
            const uint4* Kb = reinterpret_cast<const uint4*>(
                K2 + (size_t)(n * P + band * RB) * (P / 2));

            uint4 kk[RB];   // K band, registers, reused by both passes
            bool inc = (cnt < CB);
            uint4* cb = kcache + cnt * BAND_U4;

            if (inc && it > 0) {
                // cached band: read own per-thread slots from smem
#pragma unroll
                for (int i = 0; i < RB; i++)
                    kk[i] = cb[i * 256 + tid];
            } else {
#pragma unroll
                for (int i = 0; i < RB; i++)
                    kk[i] = Kb[(size_t)i * 256 + tid];
                if (inc) {       // populate cache on iteration 0
#pragma unroll
                    for (int i = 0; i < RB; i++)
                        cb[i * 256 + tid] = kk[i];
                }
            }

            // pass 1: row dots with register b, warp shfl-reduce
#pragma unroll
            for (int i = 0; i < RB; i++) {
                float2 f0 = __half22float2(*reinterpret_cast<__half2*>(&kk[i].x));
                float2 f1 = __half22float2(*reinterpret_cast<__half2*>(&kk[i].y));
                float2 f2 = __half22float2(*reinterpret_cast<__half2*>(&kk[i].z));
                float2 f3 = __half22float2(*reinterpret_cast<__half2*>(&kk[i].w));
                float s = f0.x * B0.x;
                s = fmaf(f0.y, B0.y, s);
                s = fmaf(f1.x, B0.z, s);
                s = fmaf(f1.y, B0.w, s);
                s = fmaf(f2.x, B1.x, s);
                s = fmaf(f2.y, B1.y, s);
                s = fmaf(f3.x, B1.z, s);
                s = fmaf(f3.y, B1.w, s);
#pragma unroll
                for (int o = 16; o; o >>= 1)
                    s += __shfl_down_sync(0xffffffffu, s, o);
                if (l == 0) wsum[i * 8 + w] = s;
            }
            __syncthreads();

            if (tid < RB) {
                float s = 0.f;
#pragma unroll
                for (int j = 0; j < 8; j++) s += wsum[tid * 8 + j];
                int row = band * RB + tid;
                float av = __fdividef(__ldg(mu + n * P + row) + 1e-8f, s);
                ash[tid] = av;
                if (it == NITER - 1) a_buf[n * P + row] = av;
            }
            __syncthreads();

            // pass 2: column partials from the SAME registers
#pragma unroll
            for (int i = 0; i < RB; i++) {
                float ai = ash[i];
                float2 f0 = __half22float2(*reinterpret_cast<__half2*>(&kk[i].x));
                float2 f1 = __half22float2(*reinterpret_cast<__half2*>(&kk[i].y));
                float2 f2 = __half22float2(*reinterpret_cast<__half2*>(&kk[i].z));
                float2 f3 = __half22float2(*reinterpret_cast<__half2*>(&kk[i].w));
                c0 = fmaf(ai, f0.x, c0);  c1 = fmaf(ai, f0.y, c1);
                c2 = fmaf(ai, f1.x, c2);  c3 = fmaf(ai, f1.y, c3);
                c4 = fmaf(ai, f2.x, c4);  c5 = fmaf(ai, f2.y, c5);
                c6 = fmaf(ai, f3.x, c6);  c7 = fmaf(ai, f3.y, c7);
            }
            // ash/wsum rewritten only after the next band's own syncs.
        }

        // publish this block's column partials
        float* wp = partials + (size_t)(n * Bb + r) * P + tid * 8;
        *reinterpret_cast<float4*>(wp)     = make_float4(c0, c1, c2, c3);
        *reinterpret_cast<float4*>(wp + 4) = make_float4(c4, c5, c6, c7);

        batch_sync(n, Bb);

        // distributed b-reduce (batch-local): 4 threads per column entry,
        // 4 independent accumulators for MLP, shfl-combine in 4-lane groups.
        {
            int t = r * TPB + tid;              // 0 .. Bb*256-1
            int e = t >> 2;                     // column entry
            int q = t & 3;                      // lane within 4-group
            float s0 = 0.f, s1 = 0.f, s2 = 0.f, s3 = 0.f;
            if (e < P) {
                const float* pp = partials + (size_t)n * Bb * P + e;
                int k = q;
                for (; k + 12 < Bb; k += 16) {
                    s0 += __ldcg(pp + (size_t)k * P);
                    s1 += __ldcg(pp + (size_t)(k + 4) * P);
                    s2 += __ldcg(pp + (size_t)(k + 8) * P);
                    s3 += __ldcg(pp + (size_t)(k + 12) * P);
                }
                for (; k < Bb; k += 4) s0 += __ldcg(pp + (size_t)k * P);
            }
            float s = (s0 + s1) + (s2 + s3);
            s += __shfl_down_sync(0xffffffffu, s, 1, 4);
            s += __shfl_down_sync(0xffffffffu, s, 2, 4);
            if (e < P && q == 0)
                b_buf[n * P + e] = __fdividef(__ldg(nu + n * P + e) + 1e-8f, s);
        }

        batch_sync(n, Bb);
    }
}

// ---------------------------------------------------------------------------
// pi = exp(ln a + ln b - 10*C) from ORIGINAL fp32 C; cost partials; C copy
__global__ __launch_bounds__(256) void k_epi(const float* __restrict__ C,
                                             float* __restrict__ pi_out,
                                             float* __restrict__ c_out) {
    int n    = blockIdx.y;
    int row0 = blockIdx.x * 16;
    __shared__ float lbsh[P];
    __shared__ float sred[256];
    for (int j = threadIdx.x; j < P; j += 256)
        lbsh[j] = __logf(b_buf[n * P + j]);
    __syncthreads();
    float local = 0.0f;
    for (int r = 0; r < 16; r++) {
        int row = row0 + r;
        float la = __logf(a_buf[n * P + row]);
        size_t base = ((size_t)n * P + row) * P;
        const float4* Cr = reinterpret_cast<const float4*>(C + base);
        float4* Pr = pi_out ? reinterpret_cast<float4*>(pi_out + base) : nullptr;
        float4* Or = c_out  ? reinterpret_cast<float4*>(c_out  + base) : nullptr;
        for (int q = threadIdx.x; q < P / 4; q += 256) {
            float4 c = __ldcs(Cr + q);
            int j = q * 4;
            float4 pi;
            pi.x = __expf(la + lbsh[j]     - INV_EPS * c.x);
            pi.y = __expf(la + lbsh[j + 1] - INV_EPS * c.y);
            pi.z = __expf(la + lbsh[j + 2] - INV_EPS * c.z);
            pi.w = __expf(la + lbsh[j + 3] - INV_EPS * c.w);
            if (Pr) __stcs(Pr + q, pi);
            if (Or) __stcs(Or + q, c);
            local += pi.x * c.x + pi.y * c.y + pi.z * c.z + pi.w * c.w;
        }
    }
    sred[threadIdx.x] = local;
    __syncthreads();
    for (int o = 128; o; o >>= 1) {
        if (threadIdx.x < o) sred[threadIdx.x] += sred[threadIdx.x + o];
        __syncthreads();
    }
    if (threadIdx.x == 0) cost_part[n * 128 + blockIdx.x] = sred[0];
}

__global__ __launch_bounds__(128) void k_cost(float* __restrict__ out) {
    int n = blockIdx.x;
    __shared__ float s[128];
    s[threadIdx.x] = cost_part[n * 128 + threadIdx.x];
    __syncthreads();
    for (int o = 64; o; o >>= 1) {
        if (threadIdx.x < o) s[threadIdx.x] += s[threadIdx.x + o];
        __syncthreads();
    }
    if (threadIdx.x == 0) out[n] = s[0];
}

// ---------------------------------------------------------------------------
extern "C" void kernel_launch(void* const* d_in, const int* in_sizes, int n_in,
                              void* d_out, int out_size) {
    const float* C  = (const float*)d_in[0];
    const float* mu = (const float*)d_in[1];
    const float* nu = (const float*)d_in[2];
    float* out = (float*)d_out;

    const long long PI_ELEMS = (long long)N_B * P * P;  // 33554432
    float* pi_out = nullptr;
    float* c_out  = nullptr;
    if ((long long)out_size >= 8 + PI_ELEMS)     pi_out = out + 8;
    if ((long long)out_size >= 8 + 2 * PI_ELEMS) c_out  = out + 8 + PI_ELEMS;

    const int MAIN_SMEM = CB * BAND_U4 * 16 + 64 * 4 + 8 * 4 + 32;  // ~96.4 KB
    static int G = 0, Bb = 0;
    if (G == 0) {   // host-side, deterministic per process
        cudaFuncSetAttribute(k_main, cudaFuncAttributeMaxDynamicSharedMemorySize,
                             MAIN_SMEM);
        int dev = 0, nsm = 148, maxb = 1;
        cudaGetDevice(&dev);
        cudaDeviceGetAttribute(&nsm, cudaDevAttrMultiProcessorCount, dev);
        cudaOccupancyMaxActiveBlocksPerMultiprocessor(&maxb, k_main, TPB, MAIN_SMEM);
        if (maxb < 1) maxb = 1;
        if (maxb > 2) maxb = 2;
        long long tot = (long long)nsm * maxb;
        Bb = (int)(tot / N_B);
        if (Bb > MAXBB) Bb = MAXBB;
        if (Bb < 32) Bb = 32;   // b-reduce needs Bb*256 >= 4*P threads
        G = Bb * N_B;
    }

    k_prep<<<32768, 256>>>(C);
    k_main<<<G, TPB, MAIN_SMEM>>>(mu, nu, Bb);
    k_epi<<<dim3(128, N_B), 256>>>(C, pi_out, c_out);
    k_cost<<<N_B, 128>>>(out);
}